// round 6
// baseline (speedup 1.0000x reference)
#include <cuda_runtime.h>

#define NN 8192
#define DD 64
#define EK 262144
#define EHK 262144
#define TAB 2048
#define CAP 256
#define MB 148                 // matvec worker blocks per phase
#define EB 592                 // edge worker blocks (phase A)
#define EWARPS (EB * 8)
#define MSPLIT 4096            // matvec rows done in phase A

// Scratch (device globals: allocation-free)
__device__ float g_sk[NN * DD];      // normalized state_K
__device__ float g_g[NN];            // tanh(state_H)
__device__ float g_fHa[NN];          // f_H edge accumulator
__device__ float g_tab[TAB + 1];     // dE(s) lookup table
__device__ int   g_cnt[NN * 32];     // per-row payload counters (128B padded)
__device__ int2  g_list[NN * CAP];   // (src_row, coef_bits) payloads (16MB)

__device__ __forceinline__ float warp_sum(float v) {
    #pragma unroll
    for (int o = 16; o; o >>= 1) v += __shfl_xor_sync(0xFFFFFFFFu, v, o);
    return v;
}

// --- prep: normalize sk rows, g=tanh(sH), zero cnt/fHa, build dE table.
__global__ void prep_kernel(const float* __restrict__ sH, const float* __restrict__ sK,
                            const float* __restrict__ w1, const float* __restrict__ b1,
                            const float* __restrict__ w2) {
    int warp = threadIdx.x >> 5, lane = threadIdx.x & 31;
    int row = blockIdx.x * 8 + warp;
    float2 v = ((const float2*)(sK + row * DD))[lane];
    float ss = warp_sum(v.x * v.x + v.y * v.y);
    float inv = rsqrtf(ss);
    ((float2*)(g_sk + row * DD))[lane] = make_float2(v.x * inv, v.y * inv);
    if (lane == 0) g_g[row] = tanhf(sH[row]);

    int gt = blockIdx.x * 256 + threadIdx.x;          // 0..262143 == NN*32
    g_cnt[gt] = 0;
    if (gt < NN) g_fHa[gt] = 0.f;
    if (gt <= TAB) {
        float s = gt * (2.0f / TAB) - 1.0f;
        float acc = 0.f;
        #pragma unroll 8
        for (int h = 0; h < 64; h++)
            acc += tanhf(s * __ldg(w1 + h) + __ldg(b1 + h)) * __ldg(w2 + h);
        g_tab[gt] = acc;
    }
}

// matvec body: f_H[row] = -sH[row] + W_H[row,:] @ g (+fHa if requested)
__device__ __forceinline__ void matvec_rows(int beg, int end,
                                            const float* __restrict__ sH,
                                            const float* __restrict__ W,
                                            float* __restrict__ out, bool addFHa) {
    __shared__ float rr[8];
    int lane = threadIdx.x & 31, warp = threadIdx.x >> 5;
    const float4* g4 = (const float4*)g_g;
    for (int row = beg + blockIdx.x; row < end; row += MB) {
        const float4* Wr = (const float4*)(W + (size_t)row * NN);
        float acc = 0.f;
        #pragma unroll
        for (int it = 0; it < 8; it++) {
            int k = threadIdx.x + it * 256;
            float4 w = __ldcs(Wr + k);
            float4 g = g4[k];
            acc += w.x * g.x + w.y * g.y + w.z * g.z + w.w * g.w;
        }
        acc = warp_sum(acc);
        if (lane == 0) rr[warp] = acc;
        __syncthreads();
        if (threadIdx.x == 0) {
            float v = rr[0] + rr[1] + rr[2] + rr[3] + rr[4] + rr[5] + rr[6] + rr[7];
            out[row] = -sH[row] + v + (addFHa ? g_fHa[row] : 0.f);
        }
        __syncthreads();
    }
}

// --- phase A: edge build (dot -> coef -> payload append) + matvec rows [0,MSPLIT).
__global__ __launch_bounds__(256) void phaseA_kernel(
    const float* __restrict__ sH, const float* __restrict__ W,
    const int* __restrict__ indK, const int* __restrict__ indHK,
    float* __restrict__ out)
{
    if (blockIdx.x < MB) { matvec_rows(0, MSPLIT, sH, W, out, false); return; }

    int lane = threadIdx.x & 31, warp = threadIdx.x >> 5;
    int c = lane & 15;
    int wg = (blockIdx.x - MB) * 8 + warp;
    #pragma unroll 2
    for (int e = wg; e < EHK + EK; e += EWARPS) {
        bool isHK = e < EHK;
        int2 ij = isHK ? __ldg((const int2*)indHK + e)
                       : __ldg((const int2*)indK + (e - EHK));
        int myRow = (lane < 16) ? ij.x : ij.y;
        float4 v = __ldg((const float4*)(g_sk + myRow * DD) + c);
        float4 w;
        w.x = __shfl_xor_sync(0xFFFFFFFFu, v.x, 16);
        w.y = __shfl_xor_sync(0xFFFFFFFFu, v.y, 16);
        w.z = __shfl_xor_sync(0xFFFFFFFFu, v.z, 16);
        w.w = __shfl_xor_sync(0xFFFFFFFFu, v.w, 16);
        float d = v.x * w.x + v.y * w.y + v.z * w.z + v.w * w.w;
        d += __shfl_xor_sync(0xFFFFFFFFu, d, 1);
        d += __shfl_xor_sync(0xFFFFFFFFu, d, 2);
        d += __shfl_xor_sync(0xFFFFFFFFu, d, 4);
        d += __shfl_xor_sync(0xFFFFFFFFu, d, 8);   // s = <row_i, row_j>
        float coef;
        if (isHK) {
            float gm = __ldg(g_g + myRow);
            float gp = __shfl_xor_sync(0xFFFFFFFFu, gm, 16);
            if (lane == 0)  atomicAdd(g_fHa + ij.x, d * gp * 0.5f);  // /KAPPA_H
            if (lane == 16) atomicAdd(g_fHa + ij.y, d * gp * 0.5f);
            coef = -0.5f * gm * gp;                                  // -G/KAPPA_K
        } else {
            float t = (fminf(fmaxf(d, -1.f), 1.f) + 1.f) * (TAB * 0.5f);
            int i0 = min((int)t, TAB - 1);
            float f = t - (float)i0;
            float t0 = __ldg(g_tab + i0), t1 = __ldg(g_tab + i0 + 1);
            coef = t0 + (t1 - t0) * f;                               // dE(s)
        }
        if (lane == 0 || lane == 16) {
            int dst = myRow;
            int src = (lane == 0) ? ij.y : ij.x;
            int slot = atomicAdd(g_cnt + dst * 32, 1);
            if (slot < CAP)
                g_list[dst * CAP + slot] = make_int2(src, __float_as_int(coef));
        }
    }
}

// --- phase B: gather + finalize (warp-per-row, 8 rows/block) + matvec rows [MSPLIT,NN).
__global__ __launch_bounds__(256) void phaseB_kernel(
    const float* __restrict__ sH, const float* __restrict__ W,
    const float* __restrict__ omega, float* __restrict__ out)
{
    if (blockIdx.x < MB) { matvec_rows(MSPLIT, NN, sH, W, out, true); return; }

    __shared__ float A[DD * DD];      // antisymmetrized omega
    __shared__ float srow[8 * DD];
    __shared__ int2  buf[8][32];
    for (int k = threadIdx.x; k < DD * DD; k += 256) {
        int rI = k >> 6, cc = k & 63;
        A[k] = 0.5f * (__ldg(omega + k) - __ldg(omega + cc * DD + rI));
    }
    __syncthreads();

    int warp = threadIdx.x >> 5, lane = threadIdx.x & 31;
    int row = (blockIdx.x - MB) * 8 + warp;
    int deg = min(g_cnt[row * 32], CAP);
    const int2* lst = g_list + row * CAP;

    float ax = 0.f, ay = 0.f;
    for (int b = 0; b < deg; b += 32) {
        int n = min(32, deg - b);
        int2 p = (lane < n) ? __ldg(lst + b + lane) : make_int2(0, 0);
        buf[warp][lane] = p;
        __syncwarp();
        if (n == 32) {
            #pragma unroll 8
            for (int k = 0; k < 32; k++) {
                int2 e = buf[warp][k];
                float cf = __int_as_float(e.y);
                float2 v = ((const float2*)(g_sk + e.x * DD))[lane];
                ax += cf * v.x; ay += cf * v.y;
            }
        } else {
            for (int k = 0; k < n; k++) {
                int2 e = buf[warp][k];
                float cf = __int_as_float(e.y);
                float2 v = ((const float2*)(g_sk + e.x * DD))[lane];
                ax += cf * v.x; ay += cf * v.y;
            }
        }
        __syncwarp();
    }

    // finalize: f_K = -acc + sk*<sk,acc> + sk @ (omega-omega^T)/2
    float2 skv = ((const float2*)(g_sk + row * DD))[lane];
    float d = warp_sum(skv.x * ax + skv.y * ay);
    ((float2*)(srow + warp * DD))[lane] = skv;
    __syncwarp();
    const float* sr = srow + warp * DD;
    const float2* A2 = (const float2*)A;
    float m0 = 0.f, m1 = 0.f;
    #pragma unroll
    for (int k = 0; k < DD; k++) {
        float sv = sr[k];
        float2 av = A2[k * 32 + lane];
        m0 += sv * av.x;
        m1 += sv * av.y;
    }
    float o0 = -ax + skv.x * d + m0;
    float o1 = -ay + skv.y * d + m1;
    ((float2*)(out + NN + row * DD))[lane] = make_float2(o0, o1);
    if (lane == 0 && row < MSPLIT) out[row] += g_fHa[row];   // finish phase-A f_H rows
}

extern "C" void kernel_launch(void* const* d_in, const int* in_sizes, int n_in,
                              void* d_out, int out_size) {
    const float* sH   = (const float*)d_in[0];
    const float* sK   = (const float*)d_in[1];
    const float* WH   = (const float*)d_in[2];
    const float* om   = (const float*)d_in[3];
    const float* w1   = (const float*)d_in[4];
    const float* b1   = (const float*)d_in[5];
    const float* w2   = (const float*)d_in[6];
    const int*  indK  = (const int*)d_in[7];
    const int*  indHK = (const int*)d_in[8];
    float* out = (float*)d_out;

    prep_kernel<<<NN / 8, 256>>>(sH, sK, w1, b1, w2);
    phaseA_kernel<<<MB + EB, 256>>>(sH, WH, indK, indHK, out);
    phaseB_kernel<<<MB + NN / 8, 256>>>(sH, WH, om, out);
}

// round 7
// speedup vs baseline: 1.0970x; 1.0970x over previous
#include <cuda_runtime.h>

#define NN 8192
#define DD 64
#define EK 262144
#define EHK 262144
#define TAB 2048
#define MB 148                 // matvec worker blocks (1 per SM)
#define EB 740                 // edge worker blocks (5 per SM)
#define EWARPS (EB * 8)        // 5920 edge warps

// Scratch (device globals: allocation-free)
__device__ float g_sk[NN * DD];   // normalized state_K
__device__ float g_g[NN];         // tanh(state_H)
__device__ float g_fK[NN * DD];   // f_K edge accumulator
__device__ float g_fHa[NN];       // f_H edge accumulator
__device__ float g_tab[TAB + 1];  // dE(s) lookup table, s in [-1,1]

// NOTE: no "memory" clobber — g_fK/g_fHa are never read in this kernel, and
// removing the fence lets ptxas pipeline loads across reds (MLP across edges).
__device__ __forceinline__ void red4(float* p, float a, float b, float c, float d) {
    asm volatile("red.global.add.v4.f32 [%0], {%1,%2,%3,%4};"
                 :: "l"(p), "f"(a), "f"(b), "f"(c), "f"(d));
}
__device__ __forceinline__ void red1(float* p, float a) {
    asm volatile("red.global.add.f32 [%0], %1;" :: "l"(p), "f"(a));
}

__device__ __forceinline__ float warp_sum(float v) {
    #pragma unroll
    for (int o = 16; o; o >>= 1) v += __shfl_xor_sync(0xFFFFFFFFu, v, o);
    return v;
}

// --- prep: normalize state_K rows, g=tanh(sH), zero accumulators, build table.
__global__ void prep_kernel(const float* __restrict__ sH, const float* __restrict__ sK,
                            const float* __restrict__ w1, const float* __restrict__ b1,
                            const float* __restrict__ w2) {
    int warp = threadIdx.x >> 5, lane = threadIdx.x & 31;
    int row = blockIdx.x * 8 + warp;
    float2 v = ((const float2*)(sK + row * DD))[lane];
    float ss = warp_sum(v.x * v.x + v.y * v.y);
    float inv = rsqrtf(ss);
    ((float2*)(g_sk + row * DD))[lane] = make_float2(v.x * inv, v.y * inv);
    if (lane == 0) g_g[row] = tanhf(sH[row]);

    int gt = blockIdx.x * 256 + threadIdx.x;          // 0..262143
    if (gt < NN * DD / 4) ((float4*)g_fK)[gt] = make_float4(0.f, 0.f, 0.f, 0.f);
    if (gt < NN / 4)      ((float4*)g_fHa)[gt] = make_float4(0.f, 0.f, 0.f, 0.f);
    if (gt <= TAB) {
        float s = gt * (2.0f / TAB) - 1.0f;
        float acc = 0.f;
        #pragma unroll 8
        for (int h = 0; h < 64; h++)
            acc += tanhf(s * __ldg(w1 + h) + __ldg(b1 + h)) * __ldg(w2 + h);
        g_tab[gt] = acc;
    }
}

// --- mega: persistent workers. Blocks 0..MB-1: matvec rows (grid-stride).
//     Blocks MB..MB+EB-1: edges (warp grid-stride over EHK+EK jobs).
__global__ __launch_bounds__(256, 6) void mega_kernel(
    const float* __restrict__ sH, const float* __restrict__ W,
    const int* __restrict__ indK, const int* __restrict__ indHK,
    float* __restrict__ out)
{
    int lane = threadIdx.x & 31, warp = threadIdx.x >> 5;

    if (blockIdx.x < MB) {
        // ---- matvec worker: keeps DRAM saturated for whole kernel duration.
        __shared__ float rr[8];
        const float4* g4 = (const float4*)g_g;
        for (int row = blockIdx.x; row < NN; row += MB) {
            const float4* Wr = (const float4*)(W + (size_t)row * NN);
            float acc = 0.f;
            #pragma unroll
            for (int it = 0; it < 8; it++) {
                int k = threadIdx.x + it * 256;
                float4 w = __ldcs(Wr + k);     // stream: don't pollute L2
                float4 g = g4[k];
                acc += w.x * g.x + w.y * g.y + w.z * g.z + w.w * g.w;
            }
            acc = warp_sum(acc);
            if (lane == 0) rr[warp] = acc;
            __syncthreads();
            if (threadIdx.x == 0) {
                float v = rr[0] + rr[1] + rr[2] + rr[3] + rr[4] + rr[5] + rr[6] + rr[7];
                out[row] = -sH[row] + v;
            }
            __syncthreads();
        }
        return;
    }

    // ---- edge worker: warp-per-edge, half-warp per endpoint, pipelined.
    int c = lane & 15;                    // float4 chunk within row
    int wg = (blockIdx.x - MB) * 8 + warp;
    #pragma unroll 4
    for (int e = wg; e < EHK + EK; e += EWARPS) {
        bool isHK = e < EHK;
        int2 ij = isHK ? __ldg((const int2*)indHK + e)
                       : __ldg((const int2*)indK + (e - EHK));
        int myRow = (lane < 16) ? ij.x : ij.y;
        float4 v = __ldg((const float4*)(g_sk + myRow * DD) + c);
        float4 w;                          // partner row chunk
        w.x = __shfl_xor_sync(0xFFFFFFFFu, v.x, 16);
        w.y = __shfl_xor_sync(0xFFFFFFFFu, v.y, 16);
        w.z = __shfl_xor_sync(0xFFFFFFFFu, v.z, 16);
        w.w = __shfl_xor_sync(0xFFFFFFFFu, v.w, 16);
        float d = v.x * w.x + v.y * w.y + v.z * w.z + v.w * w.w;
        d += __shfl_xor_sync(0xFFFFFFFFu, d, 1);
        d += __shfl_xor_sync(0xFFFFFFFFu, d, 2);
        d += __shfl_xor_sync(0xFFFFFFFFu, d, 4);
        d += __shfl_xor_sync(0xFFFFFFFFu, d, 8);   // s = <row_i, row_j>
        float coef;
        if (isHK) {
            float gm = __ldg(g_g + myRow);
            float gp = __shfl_xor_sync(0xFFFFFFFFu, gm, 16);
            if ((lane & 15) == 0)                       // lanes 0 and 16
                red1(g_fHa + myRow, d * gp * 0.5f);     // /KAPPA_H
            coef = -0.5f * gm * gp;                     // -G/KAPPA_K
        } else {
            float t = (fminf(fmaxf(d, -1.f), 1.f) + 1.f) * (TAB * 0.5f);
            int i0 = min((int)t, TAB - 1);
            float f = t - (float)i0;
            float t0 = __ldg(g_tab + i0), t1 = __ldg(g_tab + i0 + 1);
            coef = t0 + (t1 - t0) * f;                  // dE(s)
        }
        // endpoint myRow accumulates coef * partner_row (chunks already in w)
        red4(g_fK + myRow * DD + c * 4, coef * w.x, coef * w.y, coef * w.z, coef * w.w);
    }
}

// --- finalize: f_H += fHacc; f_K = -acc + sk*<sk,acc> + sk @ (omega-omega^T)/2.
__global__ void fin_kernel(const float* __restrict__ omega, float* __restrict__ out) {
    __shared__ float A[DD * DD];      // antisymmetrized omega
    __shared__ float srow[8 * DD];
    for (int k = threadIdx.x; k < DD * DD; k += 256) {
        int rI = k >> 6, cc = k & 63;
        A[k] = 0.5f * (omega[k] - omega[cc * DD + rI]);
    }
    __syncthreads();
    int warp = threadIdx.x >> 5, lane = threadIdx.x & 31;
    int row = blockIdx.x * 8 + warp;
    if (lane == 0) out[row] += g_fHa[row];            // finish f_H
    float2 skv = ((const float2*)(g_sk + row * DD))[lane];
    float2 fv  = ((const float2*)(g_fK + row * DD))[lane];
    float d = warp_sum(skv.x * fv.x + skv.y * fv.y);
    ((float2*)(srow + warp * DD))[lane] = skv;
    __syncwarp();
    const float* sr = srow + warp * DD;
    const float2* A2 = (const float2*)A;
    float m0 = 0.f, m1 = 0.f;
    #pragma unroll
    for (int k = 0; k < DD; k++) {
        float sv = sr[k];
        float2 av = A2[k * 32 + lane];
        m0 += sv * av.x;
        m1 += sv * av.y;
    }
    float o0 = -fv.x + skv.x * d + m0;
    float o1 = -fv.y + skv.y * d + m1;
    ((float2*)(out + NN + row * DD))[lane] = make_float2(o0, o1);
}

extern "C" void kernel_launch(void* const* d_in, const int* in_sizes, int n_in,
                              void* d_out, int out_size) {
    const float* sH   = (const float*)d_in[0];
    const float* sK   = (const float*)d_in[1];
    const float* WH   = (const float*)d_in[2];
    const float* om   = (const float*)d_in[3];
    const float* w1   = (const float*)d_in[4];
    const float* b1   = (const float*)d_in[5];
    const float* w2   = (const float*)d_in[6];
    const int*  indK  = (const int*)d_in[7];
    const int*  indHK = (const int*)d_in[8];
    float* out = (float*)d_out;

    prep_kernel<<<NN / 8, 256>>>(sH, sK, w1, b1, w2);
    mega_kernel<<<MB + EB, 256>>>(sH, WH, indK, indHK, out);
    fin_kernel<<<NN / 8, 256>>>(om, out);
}

// round 8
// speedup vs baseline: 1.5326x; 1.3971x over previous
#include <cuda_runtime.h>

#define NN 8192
#define DD 64
#define EK 262144
#define EHK 262144
#define TAB 2048
#define MB 296                 // matvec worker blocks (2 per SM)
#define EB 592                 // edge worker blocks (4 per SM)
#define EWARPS (EB * 8)        // 4736 edge warps

// Scratch (device globals: allocation-free)
__device__ float g_sk[NN * DD];   // normalized state_K
__device__ float g_g[NN];         // tanh(state_H)
__device__ float g_fK[NN * DD];   // f_K edge accumulator
__device__ float g_fHa[NN];       // f_H edge accumulator
__device__ float g_tab[TAB + 1];  // dE(s) lookup table, s in [-1,1]

// No "memory" clobber: g_fK/g_fHa are write-only in mega; lets ptxas pipeline
// the next iteration's loads past this red.
__device__ __forceinline__ void red4(float* p, float a, float b, float c, float d) {
    asm volatile("red.global.add.v4.f32 [%0], {%1,%2,%3,%4};"
                 :: "l"(p), "f"(a), "f"(b), "f"(c), "f"(d));
}
__device__ __forceinline__ void red1(float* p, float a) {
    asm volatile("red.global.add.f32 [%0], %1;" :: "l"(p), "f"(a));
}

__device__ __forceinline__ float warp_sum(float v) {
    #pragma unroll
    for (int o = 16; o; o >>= 1) v += __shfl_xor_sync(0xFFFFFFFFu, v, o);
    return v;
}

// --- prep: normalize state_K rows, g=tanh(sH), zero accumulators, build table.
__global__ void prep_kernel(const float* __restrict__ sH, const float* __restrict__ sK,
                            const float* __restrict__ w1, const float* __restrict__ b1,
                            const float* __restrict__ w2) {
    int warp = threadIdx.x >> 5, lane = threadIdx.x & 31;
    int row = blockIdx.x * 8 + warp;
    float2 v = ((const float2*)(sK + row * DD))[lane];
    float ss = warp_sum(v.x * v.x + v.y * v.y);
    float inv = rsqrtf(ss);
    ((float2*)(g_sk + row * DD))[lane] = make_float2(v.x * inv, v.y * inv);
    if (lane == 0) g_g[row] = tanhf(sH[row]);

    int gt = blockIdx.x * 256 + threadIdx.x;          // 0..262143
    if (gt < NN * DD / 4) ((float4*)g_fK)[gt] = make_float4(0.f, 0.f, 0.f, 0.f);
    if (gt < NN / 4)      ((float4*)g_fHa)[gt] = make_float4(0.f, 0.f, 0.f, 0.f);
    if (gt <= TAB) {
        float s = gt * (2.0f / TAB) - 1.0f;
        float acc = 0.f;
        #pragma unroll 8
        for (int h = 0; h < 64; h++)
            acc += tanhf(s * __ldg(w1 + h) + __ldg(b1 + h)) * __ldg(w2 + h);
        g_tab[gt] = acc;
    }
}

// --- mega: persistent workers. Blocks 0..MB-1: matvec rows (grid-stride).
//     Blocks MB..MB+EB-1: edges (warp grid-stride over EHK+EK jobs).
__global__ __launch_bounds__(256, 6) void mega_kernel(
    const float* __restrict__ sH, const float* __restrict__ W,
    const int* __restrict__ indK, const int* __restrict__ indHK,
    float* __restrict__ out)
{
    int lane = threadIdx.x & 31, warp = threadIdx.x >> 5;

    if (blockIdx.x < MB) {
        // ---- matvec worker: rows blockIdx.x, +MB, ... keeps DRAM saturated.
        __shared__ float rr[8];
        const float4* g4 = (const float4*)g_g;
        for (int row = blockIdx.x; row < NN; row += MB) {
            const float4* Wr = (const float4*)(W + (size_t)row * NN);
            float acc = 0.f;
            #pragma unroll
            for (int it = 0; it < 8; it++) {
                int k = threadIdx.x + it * 256;
                float4 w = __ldcs(Wr + k);     // stream: don't pollute L2
                float4 g = g4[k];
                acc += w.x * g.x + w.y * g.y + w.z * g.z + w.w * g.w;
            }
            acc = warp_sum(acc);
            if (lane == 0) rr[warp] = acc;
            __syncthreads();
            if (threadIdx.x == 0) {
                float v = rr[0] + rr[1] + rr[2] + rr[3] + rr[4] + rr[5] + rr[6] + rr[7];
                out[row] = -sH[row] + v;
            }
            __syncthreads();
        }
        return;
    }

    // ---- edge worker: warp-per-edge, half-warp per endpoint.
    int c = lane & 15;                    // float4 chunk within row
    int wg = (blockIdx.x - MB) * 8 + warp;
    #pragma unroll 2
    for (int e = wg; e < EHK + EK; e += EWARPS) {
        bool isHK = e < EHK;
        int2 ij = isHK ? __ldg((const int2*)indHK + e)
                       : __ldg((const int2*)indK + (e - EHK));
        int myRow = (lane < 16) ? ij.x : ij.y;
        float4 v = __ldg((const float4*)(g_sk + myRow * DD) + c);
        float4 w;                          // partner row chunk
        w.x = __shfl_xor_sync(0xFFFFFFFFu, v.x, 16);
        w.y = __shfl_xor_sync(0xFFFFFFFFu, v.y, 16);
        w.z = __shfl_xor_sync(0xFFFFFFFFu, v.z, 16);
        w.w = __shfl_xor_sync(0xFFFFFFFFu, v.w, 16);
        float d = v.x * w.x + v.y * w.y + v.z * w.z + v.w * w.w;
        d += __shfl_xor_sync(0xFFFFFFFFu, d, 1);
        d += __shfl_xor_sync(0xFFFFFFFFu, d, 2);
        d += __shfl_xor_sync(0xFFFFFFFFu, d, 4);
        d += __shfl_xor_sync(0xFFFFFFFFu, d, 8);   // s = <row_i, row_j>
        float coef;
        if (isHK) {
            float gm = __ldg(g_g + myRow);
            float gp = __shfl_xor_sync(0xFFFFFFFFu, gm, 16);
            if ((lane & 15) == 0)                       // lanes 0 and 16
                red1(g_fHa + myRow, d * gp * 0.5f);     // /KAPPA_H
            coef = -0.5f * gm * gp;                     // -G/KAPPA_K
        } else {
            float t = (fminf(fmaxf(d, -1.f), 1.f) + 1.f) * (TAB * 0.5f);
            int i0 = min((int)t, TAB - 1);
            float f = t - (float)i0;
            float t0 = __ldg(g_tab + i0), t1 = __ldg(g_tab + i0 + 1);
            coef = t0 + (t1 - t0) * f;                  // dE(s)
        }
        // endpoint myRow accumulates coef * partner_row (chunks already in w)
        red4(g_fK + myRow * DD + c * 4, coef * w.x, coef * w.y, coef * w.z, coef * w.w);
    }
}

// --- finalize: f_H += fHacc; f_K = -acc + sk*<sk,acc> + sk @ (omega-omega^T)/2.
__global__ void fin_kernel(const float* __restrict__ omega, float* __restrict__ out) {
    __shared__ float A[DD * DD];      // antisymmetrized omega
    __shared__ float srow[8 * DD];
    for (int k = threadIdx.x; k < DD * DD; k += 256) {
        int rI = k >> 6, cc = k & 63;
        A[k] = 0.5f * (omega[k] - omega[cc * DD + rI]);
    }
    __syncthreads();
    int warp = threadIdx.x >> 5, lane = threadIdx.x & 31;
    int row = blockIdx.x * 8 + warp;
    if (lane == 0) out[row] += g_fHa[row];            // finish f_H
    float2 skv = ((const float2*)(g_sk + row * DD))[lane];
    float2 fv  = ((const float2*)(g_fK + row * DD))[lane];
    float d = warp_sum(skv.x * fv.x + skv.y * fv.y);
    ((float2*)(srow + warp * DD))[lane] = skv;
    __syncwarp();
    const float* sr = srow + warp * DD;
    const float2* A2 = (const float2*)A;
    float m0 = 0.f, m1 = 0.f;
    #pragma unroll
    for (int k = 0; k < DD; k++) {
        float sv = sr[k];
        float2 av = A2[k * 32 + lane];
        m0 += sv * av.x;
        m1 += sv * av.y;
    }
    float o0 = -fv.x + skv.x * d + m0;
    float o1 = -fv.y + skv.y * d + m1;
    ((float2*)(out + NN + row * DD))[lane] = make_float2(o0, o1);
}

extern "C" void kernel_launch(void* const* d_in, const int* in_sizes, int n_in,
                              void* d_out, int out_size) {
    const float* sH   = (const float*)d_in[0];
    const float* sK   = (const float*)d_in[1];
    const float* WH   = (const float*)d_in[2];
    const float* om   = (const float*)d_in[3];
    const float* w1   = (const float*)d_in[4];
    const float* b1   = (const float*)d_in[5];
    const float* w2   = (const float*)d_in[6];
    const int*  indK  = (const int*)d_in[7];
    const int*  indHK = (const int*)d_in[8];
    float* out = (float*)d_out;

    prep_kernel<<<NN / 8, 256>>>(sH, sK, w1, b1, w2);
    mega_kernel<<<MB + EB, 256>>>(sH, WH, indK, indHK, out);
    fin_kernel<<<NN / 8, 256>>>(om, out);
}